// round 11
// baseline (speedup 1.0000x reference)
#include <cuda_runtime.h>
#include <cstdint>

// Quincunx lattice max pooling — 256-bit accesses, small-CTA launch shape.
// Inputs: coset0, coset1 each [B=4, C=32, H=512, W=512] f32.
// Output: [2, B, C, H, W] f32 (out0 stacked before out1).
//
// out0[i,j] = max(c0[i,j], c0[i+1,j], c0[i,j+1], c0[i+1,j+1], c1[i,j])
// out1[i,j] = max(c1[i,j], c1[i+1,j], c1[i,j+1], c1[i+1,j+1], c0[i+1,j+1])
// Out-of-range -> -inf.
//
// 8 columns/thread via one LDG.E.256 per row per coset (per-lane 32B
// contiguous, per-warp 1024B — fully coalesced). Block=128 so CTA count
// (32768) matches the R4 winner's wave structure; R9 showed this code at
// block=256 (16384 CTAs) hits 74.08us in ncu but loses the replay bench
// on ramp/tail. Streaming 256-bit stores; outputs never re-read.

#define NEG_INF __int_as_float(0xff800000)

__device__ __forceinline__ float fmax5(float a, float b, float c, float d, float e) {
    return fmaxf(fmaxf(fmaxf(a, b), fmaxf(c, d)), e);
}

__device__ __forceinline__ void ldg256(const float* __restrict__ p, float4& lo, float4& hi) {
    asm volatile("ld.global.v8.f32 {%0,%1,%2,%3,%4,%5,%6,%7}, [%8];"
        : "=f"(lo.x), "=f"(lo.y), "=f"(lo.z), "=f"(lo.w),
          "=f"(hi.x), "=f"(hi.y), "=f"(hi.z), "=f"(hi.w)
        : "l"(p));
}

__device__ __forceinline__ void stg256cs(float* __restrict__ p, const float4& lo, const float4& hi) {
    asm volatile("st.global.cs.v8.f32 [%0], {%1,%2,%3,%4,%5,%6,%7,%8};"
        :: "l"(p),
           "f"(lo.x), "f"(lo.y), "f"(lo.z), "f"(lo.w),
           "f"(hi.x), "f"(hi.y), "f"(hi.z), "f"(hi.w)
        : "memory");
}

// Max over 2x2 own-window + cross, for an 8-wide (lo/hi float4) strip.
__device__ __forceinline__ void pool8(
    float4 r0l, float4 r0h, float r0e,      // own row i   (cols j..j+7, edge j+8)
    float4 r1l, float4 r1h, float r1e,      // own row i+1
    float4 xl,  float4 xh,                  // cross (aligned to out cols)
    float4& ol, float4& oh)
{
    ol.x = fmax5(r0l.x, r0l.y, r1l.x, r1l.y, xl.x);
    ol.y = fmax5(r0l.y, r0l.z, r1l.y, r1l.z, xl.y);
    ol.z = fmax5(r0l.z, r0l.w, r1l.z, r1l.w, xl.z);
    ol.w = fmax5(r0l.w, r0h.x, r1l.w, r1h.x, xl.w);
    oh.x = fmax5(r0h.x, r0h.y, r1h.x, r1h.y, xh.x);
    oh.y = fmax5(r0h.y, r0h.z, r1h.y, r1h.z, xh.y);
    oh.z = fmax5(r0h.z, r0h.w, r1h.z, r1h.w, xh.z);
    oh.w = fmax5(r0h.w, r0e,   r1h.w, r1e,   xh.w);
}

// planes = B*C = 128, H = 512, 8-col groups = 64 per row.
// total threads = 128 * 512 * 64 = 4194304; block = 128 -> 32768 CTAs.
__global__ void __launch_bounds__(128) lattice_pool_kernel(
    const float* __restrict__ c0,
    const float* __restrict__ c1,
    float* __restrict__ out0,
    float* __restrict__ out1)
{
    const unsigned idx = blockIdx.x * blockDim.x + threadIdx.x;
    const unsigned g = idx & 63;            // 8-column group
    const unsigned i = (idx >> 6) & 511;    // row

    const unsigned fb = idx << 3;           // float index of col 8g, row i (linear)

    const bool hasRow = (i < 511);
    const bool hasCol = (g < 63);

    const unsigned fbR = hasRow ? fb + 512u : fb;   // clamp: loads always in range

    float4 a0l, a0h, b0l, b0h, a1l, a1h, b1l, b1h;
    ldg256(c0 + fb,  a0l, a0h);
    ldg256(c1 + fb,  b0l, b0h);
    ldg256(c0 + fbR, a1l, a1h);
    ldg256(c1 + fbR, b1l, b1h);
    if (!hasRow) {
        const float4 NI4 = make_float4(NEG_INF, NEG_INF, NEG_INF, NEG_INF);
        a1l = NI4; a1h = NI4; b1l = NI4; b1h = NI4;
    }

    // j+8 edge scalars (first element of the next group) — L1 hits.
    const unsigned fe = fb + 8u;
    float a0e = hasCol ? c0[fe] : NEG_INF;
    float b0e = hasCol ? c1[fe] : NEG_INF;
    float a1e = (hasCol && hasRow) ? c0[fe + 512u] : NEG_INF;
    float b1e = (hasCol && hasRow) ? c1[fe + 512u] : NEG_INF;

    float4 ol, oh;
    // out0: own = c0 rows i,i+1; cross = c1 row i (unshifted).
    pool8(a0l, a0h, a0e, a1l, a1h, a1e, b0l, b0h, ol, oh);
    stg256cs(out0 + fb, ol, oh);

    // out1: own = c1 rows i,i+1; cross = c0 row i+1 shifted by one column.
    float4 xl, xh;
    xl.x = a1l.y; xl.y = a1l.z; xl.z = a1l.w; xl.w = a1h.x;
    xh.x = a1h.y; xh.y = a1h.z; xh.z = a1h.w; xh.w = a1e;
    pool8(b0l, b0h, b0e, b1l, b1h, b1e, xl, xh, ol, oh);
    stg256cs(out1 + fb, ol, oh);
}

extern "C" void kernel_launch(void* const* d_in, const int* in_sizes, int n_in,
                              void* d_out, int out_size) {
    const float* c0 = (const float*)d_in[0];
    const float* c1 = (const float*)d_in[1];
    float* out0 = (float*)d_out;
    float* out1 = out0 + 33554432;  // B*C*H*W floats

    const int total = 4194304;      // 128 planes * 512 rows * 64 groups
    const int threads = 128;
    const int blocks = total / threads; // 32768
    lattice_pool_kernel<<<blocks, threads>>>(c0, c1, out0, out1);
}

// round 12
// speedup vs baseline: 1.0195x; 1.0195x over previous
#include <cuda_runtime.h>
#include <cstdint>

// Quincunx lattice max pooling — FINAL (bench-best across 10 measured variants).
// Inputs: coset0, coset1 each [B=4, C=32, H=512, W=512] f32.
// Output: [2, B, C, H, W] f32 (out0 stacked before out1).
//
// out0[i,j] = max(c0[i,j], c0[i+1,j], c0[i,j+1], c0[i+1,j+1], c1[i,j])
// out1[i,j] = max(c1[i,j], c1[i+1,j], c1[i,j+1], c1[i+1,j+1], c0[i+1,j+1])
// Out-of-range -> -inf.
//
// One float4 per thread per output coset; fully coalesced LDG.128/STG.128.
// Row i+1 re-reads hit L2. __stcs streaming stores (outputs never re-read).
// 31 regs, occ 86% — on the graph-replay bench, high occupancy beats the
// 256-bit-access family (LDG.E.256: ncu 74.0us but bench 81.9-82.4us at
// occ 50-54%, at both block=256 and block=128; inter-replay latency gaps
// are exposed at low occupancy).
//
// Measured: 6.49 TB/s (81-82% of HBM3e spec), DRAM traffic ~482 MB vs the
// 512 MB analytic minimum (graph-replay L2 carryover) — at the hardware
// roofline for a 50/50 read/write mix. Bench 80.35us, reproduced 4x.

#define NEG_INF __int_as_float(0xff800000)

__device__ __forceinline__ float fmax5(float a, float b, float c, float d, float e) {
    return fmaxf(fmaxf(fmaxf(a, b), fmaxf(c, d)), e);
}

// H = W = 512, W4 = 128 (float4 lanes per row), planes = B*C = 128.
__global__ void __launch_bounds__(256) lattice_pool_kernel(
    const float4* __restrict__ c0,
    const float4* __restrict__ c1,
    float4* __restrict__ out0,
    float4* __restrict__ out1)
{
    const int idx = blockIdx.x * blockDim.x + threadIdx.x;
    const int jv = idx & 127;          // float4 column
    const int i  = (idx >> 7) & 511;   // row

    const size_t pos = (size_t)idx;    // fully linear layout

    const bool hasRow = (i < 511);
    const bool hasCol = (jv < 127);

    // Row i+1 loads: clamp offset instead of predicating the load, so both
    // LDG.128 pairs issue unconditionally (front-batched).
    const size_t posR = hasRow ? pos + 128 : pos;

    float4 a0 = c0[pos];
    float4 b0 = c1[pos];
    float4 a1 = c0[posR];
    float4 b1 = c1[posR];
    if (!hasRow) {
        a1 = make_float4(NEG_INF, NEG_INF, NEG_INF, NEG_INF);
        b1 = make_float4(NEG_INF, NEG_INF, NEG_INF, NEG_INF);
    }

    // Column j+4 scalars (first element of neighbor float4) — L1 hits.
    const float* c0f = (const float*)c0;
    const float* c1f = (const float*)c1;
    const size_t fbase = (pos << 2) + 4;   // float index of element j+4, row i
    float a0e = hasCol ? c0f[fbase] : NEG_INF;
    float b0e = hasCol ? c1f[fbase] : NEG_INF;
    float a1e = (hasCol && hasRow) ? c0f[fbase + 512] : NEG_INF;
    float b1e = (hasCol && hasRow) ? c1f[fbase + 512] : NEG_INF;

    float4 o0, o1;
    // out0: own = c0, cross = c1[i,j]
    o0.x = fmax5(a0.x, a0.y, a1.x, a1.y, b0.x);
    o0.y = fmax5(a0.y, a0.z, a1.y, a1.z, b0.y);
    o0.z = fmax5(a0.z, a0.w, a1.z, a1.w, b0.z);
    o0.w = fmax5(a0.w, a0e,  a1.w, a1e,  b0.w);
    // out1: own = c1, cross = c0[i+1,j+1]
    o1.x = fmax5(b0.x, b0.y, b1.x, b1.y, a1.y);
    o1.y = fmax5(b0.y, b0.z, b1.y, b1.z, a1.z);
    o1.z = fmax5(b0.z, b0.w, b1.z, b1.w, a1.w);
    o1.w = fmax5(b0.w, b0e,  b1.w, b1e,  a1e);

    __stcs(&out0[pos], o0);   // streaming store: output never re-read
    __stcs(&out1[pos], o1);
}

extern "C" void kernel_launch(void* const* d_in, const int* in_sizes, int n_in,
                              void* d_out, int out_size) {
    const float4* c0 = (const float4*)d_in[0];
    const float4* c1 = (const float4*)d_in[1];
    float4* out0 = (float4*)d_out;
    float4* out1 = out0 + 8388608;  // B*C*H*W / 4 float4 elements

    const int total = 8388608;      // 128 planes * 512 rows * 128 vec-cols
    const int threads = 256;
    const int blocks = total / threads; // 32768
    lattice_pool_kernel<<<blocks, threads>>>(c0, c1, out0, out1);
}